// round 5
// baseline (speedup 1.0000x reference)
#include <cuda_runtime.h>
#include <cuda_bf16.h>
#include <cstdint>

// Problem constants
#define Bb 8
#define Ss 2048
#define Dd 512
#define Qq 8
#define Kk 1024
#define Mm (Bb * Ss)   // 16384 tokens
#define CAP 8
#define MARGIN 12.0f

// Scratch (no cudaMalloc allowed)
__device__ float          g_residual[Mm * Dd];   // 32 MB fp32 residual
__device__ __nv_bfloat16  g_res16[Mm * Dd];      // 16 MB bf16 residual
__device__ __nv_bfloat16  g_cb16[Qq * Kk * Dd];  //  8 MB bf16 codebooks
__device__ float          g_c2[Qq * Kk];
__device__ float          g_loss[Qq];
// per-(nblock, token) candidate summaries
__device__ float          g_cmin[8 * Mm];          // 512 KB
__device__ int            g_ccnt[8 * Mm];          // 512 KB
__device__ uint16_t       g_cidx[8 * Mm * CAP];    // 2 MB
__device__ float          g_cval[8 * Mm * CAP];    // 4 MB

// ---------------------------------------------------------------------------
// helpers
// ---------------------------------------------------------------------------
__device__ __forceinline__ uint32_t smem_u32(const void* p) {
    uint32_t a;
    asm("{ .reg .u64 t; cvta.to.shared.u64 t, %1; cvt.u32.u64 %0, t; }"
        : "=r"(a) : "l"(p));
    return a;
}
__device__ __forceinline__ void cp16(uint32_t sa, const void* g) {
    asm volatile("cp.async.cg.shared.global [%0], [%1], 16;"
                 :: "r"(sa), "l"(g) : "memory");
}
__device__ __forceinline__ void cp_commit() {
    asm volatile("cp.async.commit_group;" ::: "memory");
}
__device__ __forceinline__ void cp_wait1() {
    asm volatile("cp.async.wait_group 1;" ::: "memory");
}
__device__ __forceinline__ void cp_wait0() {
    asm volatile("cp.async.wait_group 0;" ::: "memory");
}
__device__ __forceinline__ void ldsm4(uint32_t* r, uint32_t addr) {
    asm volatile("ldmatrix.sync.aligned.m8n8.x4.shared.b16 {%0,%1,%2,%3}, [%4];"
                 : "=r"(r[0]), "=r"(r[1]), "=r"(r[2]), "=r"(r[3])
                 : "r"(addr));
}
__device__ __forceinline__ void mma_bf16(float* c, const uint32_t* a,
                                         uint32_t b0, uint32_t b1) {
    asm volatile(
        "mma.sync.aligned.m16n8k16.row.col.f32.bf16.bf16.f32 "
        "{%0,%1,%2,%3}, {%4,%5,%6,%7}, {%8,%9}, {%0,%1,%2,%3};"
        : "+f"(c[0]), "+f"(c[1]), "+f"(c[2]), "+f"(c[3])
        : "r"(a[0]), "r"(a[1]), "r"(a[2]), "r"(a[3]), "r"(b0), "r"(b1));
}
__device__ __forceinline__ uint32_t ordkey(float f) {
    uint32_t u = __float_as_uint(f);
    return (u & 0x80000000u) ? ~u : (u | 0x80000000u);
}
__device__ __forceinline__ float orddec(uint32_t k) {
    return (k & 0x80000000u) ? __uint_as_float(k ^ 0x80000000u)
                             : __uint_as_float(~k);
}

// ---------------------------------------------------------------------------
// init: residual=x (fp32), res16=bf16(x), out=0
// ---------------------------------------------------------------------------
__global__ void init_kernel(const float4* __restrict__ x,
                            float4* __restrict__ residual,
                            __nv_bfloat162* __restrict__ res16,
                            float4* __restrict__ outq, int n4)
{
    int i = blockIdx.x * 256 + threadIdx.x;
    if (i < n4) {
        float4 v = x[i];
        residual[i] = v;
        res16[2 * i]     = __floats2bfloat162_rn(v.x, v.y);
        res16[2 * i + 1] = __floats2bfloat162_rn(v.z, v.w);
        outq[i] = make_float4(0.f, 0.f, 0.f, 0.f);
    }
}

__global__ void conv_kernel(const float4* __restrict__ in,
                            __nv_bfloat162* __restrict__ out, int n4)
{
    int i = blockIdx.x * 256 + threadIdx.x;
    if (i < n4) {
        float4 v = in[i];
        out[2 * i]     = __floats2bfloat162_rn(v.x, v.y);
        out[2 * i + 1] = __floats2bfloat162_rn(v.z, v.w);
    }
}

// ---------------------------------------------------------------------------
// c2[q][k] = ||codebook[q][k]||^2  — one warp per row (fp32 exact)
// ---------------------------------------------------------------------------
__global__ void c2_kernel(const float* __restrict__ codebooks, float* __restrict__ c2)
{
    int row  = blockIdx.x * 8 + (threadIdx.x >> 5);
    int lane = threadIdx.x & 31;
    const float4* p = (const float4*)(codebooks + (size_t)row * Dd);
    float s = 0.0f;
    #pragma unroll 4
    for (int i = lane; i < Dd / 4; i += 32) {
        float4 v = p[i];
        s += v.x * v.x + v.y * v.y + v.z * v.z + v.w * v.w;
    }
    #pragma unroll
    for (int off = 16; off; off >>= 1) s += __shfl_down_sync(0xffffffffu, s, off);
    if (lane == 0) c2[row] = s;
}

// ---------------------------------------------------------------------------
// bf16 mma.sync GEMM -> per-(token, 128-code block) min + candidate list.
// CTA 128x128, BK=64, double-buffered cp.async; same mainloop as R3.
// smem: A 2x16K | B 2x16K | rmin 512 | ccnt 512 | cidx 2K | cval 4K = 72704 B
// ---------------------------------------------------------------------------
#define GEMM_SMEM 72704

__global__ __launch_bounds__(256, 2)
void gemm_cand_kernel(const __nv_bfloat16* __restrict__ A16,
                      const __nv_bfloat16* __restrict__ B16,
                      const float* __restrict__ c2,
                      float* __restrict__ cminO,
                      int* __restrict__ ccntO,
                      uint16_t* __restrict__ cidxO,
                      float* __restrict__ cvalO)
{
    extern __shared__ char sm[];
    const uint32_t smb   = smem_u32(sm);
    const uint32_t Abase = smb;
    const uint32_t Bbase = smb + 32768;
    uint32_t* rmin = (uint32_t*)(sm + 65536);
    int*      ccnt = (int*)(sm + 66048);
    uint16_t* cidx = (uint16_t*)(sm + 66560);
    float*    cval = (float*)(sm + 68608);

    const int tid  = threadIdx.x;
    const int lane = tid & 31;
    const int warp = tid >> 5;
    const int bm = blockIdx.x * 128;
    const int bn = blockIdx.y * 128;
    const int wm = (warp & 3) * 32;
    const int wn = (warp >> 2) * 64;

    const char* gA = (const char*)(A16 + (size_t)bm * Dd);
    const char* gB = (const char*)(B16 + (size_t)bn * Dd);

    if (tid < 128) { rmin[tid] = 0xFFFFFFFFu; ccnt[tid] = 0; }

    float acc[2][8][4];
    #pragma unroll
    for (int mi = 0; mi < 2; ++mi)
        #pragma unroll
        for (int ni = 0; ni < 8; ++ni)
            #pragma unroll
            for (int j = 0; j < 4; ++j) acc[mi][ni][j] = 0.0f;

    #define LOAD_TILE(kt, buf)                                                  \
        {                                                                       \
            _Pragma("unroll")                                                   \
            for (int i = 0; i < 4; ++i) {                                       \
                int u = tid + 256 * i;                                          \
                int row = u >> 3, ch = u & 7;                                   \
                uint32_t so = (uint32_t)(row * 128 + ((ch ^ (row & 7)) * 16));  \
                size_t go = (size_t)row * (Dd * 2) + (kt) * 128 + ch * 16;      \
                cp16(Abase + (buf) * 16384 + so, gA + go);                      \
                cp16(Bbase + (buf) * 16384 + so, gB + go);                      \
            }                                                                   \
            cp_commit();                                                        \
        }

    LOAD_TILE(0, 0);

    for (int kt = 0; kt < 8; ++kt) {
        const int buf = kt & 1;
        if (kt < 7) { LOAD_TILE(kt + 1, buf ^ 1); cp_wait1(); }
        else        { cp_wait0(); }
        __syncthreads();

        #pragma unroll
        for (int s = 0; s < 4; ++s) {
            uint32_t a[2][4], b[4][4];
            const int ch = s * 2 + (lane >> 4);
            #pragma unroll
            for (int mi = 0; mi < 2; ++mi) {
                int row = wm + mi * 16 + (lane & 15);
                ldsm4(a[mi], Abase + buf * 16384 + row * 128 + ((ch ^ (row & 7)) * 16));
            }
            #pragma unroll
            for (int nj = 0; nj < 4; ++nj) {
                int row = wn + nj * 16 + (lane & 15);
                ldsm4(b[nj], Bbase + buf * 16384 + row * 128 + ((ch ^ (row & 7)) * 16));
            }
            #pragma unroll
            for (int mi = 0; mi < 2; ++mi)
                #pragma unroll
                for (int ni = 0; ni < 8; ++ni)
                    mma_bf16(acc[mi][ni], a[mi],
                             b[ni >> 1][ni & 1], b[ni >> 1][(ni & 1) + 2]);
        }
        __syncthreads();
    }

    // ---- epilogue: block-min + candidate extraction ----
    const int g = lane >> 2, t4 = lane & 3;

    float rm[4] = {3.4e38f, 3.4e38f, 3.4e38f, 3.4e38f};
    #pragma unroll
    for (int mi = 0; mi < 2; ++mi)
        #pragma unroll
        for (int ni = 0; ni < 8; ++ni)
            #pragma unroll
            for (int j = 0; j < 4; ++j) {
                int n = bn + wn + ni * 8 + 2 * t4 + (j & 1);
                float d = fmaf(-2.0f, acc[mi][ni][j], __ldg(c2 + n));
                int h = mi * 2 + (j >> 1);
                rm[h] = fminf(rm[h], d);
            }
    #pragma unroll
    for (int h = 0; h < 4; ++h) {
        int row = wm + (h >> 1) * 16 + g + (h & 1) * 8;
        atomicMin(&rmin[row], ordkey(rm[h]));
    }
    __syncthreads();

    float thr[4];
    #pragma unroll
    for (int h = 0; h < 4; ++h) {
        int row = wm + (h >> 1) * 16 + g + (h & 1) * 8;
        thr[h] = orddec(rmin[row]) + MARGIN;
    }
    #pragma unroll
    for (int mi = 0; mi < 2; ++mi)
        #pragma unroll
        for (int ni = 0; ni < 8; ++ni)
            #pragma unroll
            for (int j = 0; j < 4; ++j) {
                int n = bn + wn + ni * 8 + 2 * t4 + (j & 1);
                float d = fmaf(-2.0f, acc[mi][ni][j], __ldg(c2 + n));
                int h = mi * 2 + (j >> 1);
                if (d <= thr[h]) {
                    int row = wm + mi * 16 + g + (j >> 1) * 8;
                    int pos = atomicAdd(&ccnt[row], 1);
                    if (pos < CAP) {
                        cidx[row * CAP + pos] = (uint16_t)n;
                        cval[row * CAP + pos] = d;
                    }
                }
            }
    __syncthreads();

    if (tid < 128) {
        const size_t o = (size_t)blockIdx.y * Mm + bm + tid;
        cminO[o] = orddec(rmin[tid]);
        ccntO[o] = ccnt[tid];
        *(uint4*)(cidxO + o * CAP) = *(uint4*)(cidx + tid * CAP);
        *(float4*)(cvalO + o * CAP)     = *(float4*)(cval + tid * CAP);
        *(float4*)(cvalO + o * CAP + 4) = *(float4*)(cval + tid * CAP + 4);
    }
    #undef LOAD_TILE
}

// ---------------------------------------------------------------------------
// Fused refine + update: warp per token.
// Global min over 8 block-mins, exact fp32 rescore of candidates <= min+MARGIN,
// then residual/out/loss/index update (residual read once, in registers).
// ---------------------------------------------------------------------------
__global__ __launch_bounds__(256)
void refine_update_kernel(const float* __restrict__ cminI,
                          const int* __restrict__ ccntI,
                          const uint16_t* __restrict__ cidxI,
                          const float* __restrict__ cvalI,
                          float* __restrict__ R,
                          __nv_bfloat16* __restrict__ R16w,
                          const float* __restrict__ C,
                          const float* __restrict__ c2,
                          float* __restrict__ outq,
                          float* __restrict__ out_idx,
                          float* __restrict__ loss,
                          int qstage)
{
    const int warp = threadIdx.x >> 5, lane = threadIdx.x & 31;
    const int token = blockIdx.x * 8 + warp;

    float gm = 3.4e38f;
    int cnt_l = 0;
    if (lane < 8) {
        gm    = cminI[(size_t)lane * Mm + token];
        cnt_l = ccntI[(size_t)lane * Mm + token];
    }
    #pragma unroll
    for (int o = 16; o; o >>= 1) gm = fminf(gm, __shfl_xor_sync(~0u, gm, o));
    const float thresh = gm + MARGIN;
    const bool ovf = __ballot_sync(~0u, cnt_l > CAP) != 0;

    // residual in registers
    const float4* rrp = (const float4*)(R + (size_t)token * Dd);
    float4 rr[4];
    #pragma unroll
    for (int j = 0; j < 4; ++j) rr[j] = rrp[lane + 32 * j];

    float bd = 3.4e38f;
    int   bn = 1 << 30;

    if (!ovf) {
        #pragma unroll
        for (int b = 0; b < 8; ++b) {
            const int cb = __shfl_sync(~0u, cnt_l, b);
            const size_t base = ((size_t)b * Mm + token) * CAP;
            for (int s = 0; s < cb; ++s) {
                float val = __ldg(cvalI + base + s);
                if (val <= thresh) {
                    const int n = __ldg(cidxI + base + s);
                    const float4* cp = (const float4*)(C + (size_t)n * Dd);
                    float ss = 0.0f;
                    #pragma unroll
                    for (int j = 0; j < 4; ++j) {
                        float4 vb = cp[lane + 32 * j];
                        ss += rr[j].x * vb.x + rr[j].y * vb.y +
                              rr[j].z * vb.z + rr[j].w * vb.w;
                    }
                    #pragma unroll
                    for (int o = 16; o; o >>= 1) ss += __shfl_xor_sync(~0u, ss, o);
                    float d = fmaf(-2.0f, ss, __ldg(c2 + n));
                    if (d < bd || (d == bd && n < bn)) { bd = d; bn = n; }
                }
            }
        }
    } else {
        for (int n = 0; n < Kk; ++n) {
            const float4* cp = (const float4*)(C + (size_t)n * Dd);
            float ss = 0.0f;
            #pragma unroll
            for (int j = 0; j < 4; ++j) {
                float4 vb = cp[lane + 32 * j];
                ss += rr[j].x * vb.x + rr[j].y * vb.y +
                      rr[j].z * vb.z + rr[j].w * vb.w;
            }
            #pragma unroll
            for (int o = 16; o; o >>= 1) ss += __shfl_xor_sync(~0u, ss, o);
            float d = fmaf(-2.0f, ss, __ldg(c2 + n));
            if (d < bd || (d == bd && n < bn)) { bd = d; bn = n; }
        }
    }

    // fused update
    const float4* cp = (const float4*)(C + (size_t)bn * Dd);
    float4* rp = (float4*)(R + (size_t)token * Dd);
    float4* op = (float4*)(outq + (size_t)token * Dd);
    __nv_bfloat162* r16p = (__nv_bfloat162*)(R16w + (size_t)token * Dd);
    float lsum = 0.0f;
    #pragma unroll
    for (int j = 0; j < 4; ++j) {
        float4 cv = cp[lane + 32 * j];
        float4 nr = make_float4(rr[j].x - cv.x, rr[j].y - cv.y,
                                rr[j].z - cv.z, rr[j].w - cv.w);
        rp[lane + 32 * j] = nr;
        r16p[2 * (lane + 32 * j)]     = __floats2bfloat162_rn(nr.x, nr.y);
        r16p[2 * (lane + 32 * j) + 1] = __floats2bfloat162_rn(nr.z, nr.w);
        float4 ov = op[lane + 32 * j];
        op[lane + 32 * j] = make_float4(ov.x + cv.x, ov.y + cv.y,
                                        ov.z + cv.z, ov.w + cv.w);
        lsum += nr.x * nr.x + nr.y * nr.y + nr.z * nr.z + nr.w * nr.w;
    }
    #pragma unroll
    for (int o = 16; o; o >>= 1) lsum += __shfl_xor_sync(~0u, lsum, o);
    if (lane == 0) {
        out_idx[(size_t)token * Qq + qstage] = (float)bn;
        atomicAdd(loss, lsum);
    }
}

// ---------------------------------------------------------------------------
// Tail outputs: all_expired (zeros) then all_losses (mean over B*S*D)
// ---------------------------------------------------------------------------
__global__ void finalize_kernel(float* __restrict__ out, const float* __restrict__ loss)
{
    const size_t base = (size_t)Mm * Dd + (size_t)Mm * Qq;
    int t = threadIdx.x;
    if (t < Qq)
        out[base + t] = 0.0f;
    else if (t < 2 * Qq)
        out[base + Qq + (t - Qq)] = loss[t - Qq] * (1.0f / ((float)Mm * (float)Dd));
}

// ---------------------------------------------------------------------------
extern "C" void kernel_launch(void* const* d_in, const int* in_sizes, int n_in,
                              void* d_out, int out_size)
{
    const float* x  = (const float*)d_in[0];   // [B,S,D] f32
    const float* cb = (const float*)d_in[1];   // [Q,K,D] f32
    float* out = (float*)d_out;

    float* residual;         cudaGetSymbolAddress((void**)&residual, g_residual);
    __nv_bfloat16* res16;    cudaGetSymbolAddress((void**)&res16,    g_res16);
    __nv_bfloat16* cb16;     cudaGetSymbolAddress((void**)&cb16,     g_cb16);
    float* c2;               cudaGetSymbolAddress((void**)&c2,       g_c2);
    float* loss;             cudaGetSymbolAddress((void**)&loss,     g_loss);
    float* cmin;             cudaGetSymbolAddress((void**)&cmin,     g_cmin);
    int*   ccnt;             cudaGetSymbolAddress((void**)&ccnt,     g_ccnt);
    uint16_t* cidx;          cudaGetSymbolAddress((void**)&cidx,     g_cidx);
    float* cval;             cudaGetSymbolAddress((void**)&cval,     g_cval);

    cudaFuncSetAttribute(gemm_cand_kernel,
                         cudaFuncAttributeMaxDynamicSharedMemorySize, GEMM_SMEM);

    cudaMemsetAsync(loss, 0, Qq * sizeof(float));

    init_kernel<<<Mm * Dd / 4 / 256, 256>>>((const float4*)x, (float4*)residual,
                                            (__nv_bfloat162*)res16, (float4*)out,
                                            Mm * Dd / 4);
    conv_kernel<<<(Qq * Kk * Dd / 4 + 255) / 256, 256>>>((const float4*)cb,
                                                         (__nv_bfloat162*)cb16,
                                                         Qq * Kk * Dd / 4);
    c2_kernel<<<Qq * Kk / 8, 256>>>(cb, c2);

    for (int q = 0; q < Qq; ++q) {
        const float* Cq = cb + (size_t)q * Kk * Dd;
        const __nv_bfloat16* Cq16 = cb16 + (size_t)q * Kk * Dd;
        dim3 grid(Mm / 128, Kk / 128);
        gemm_cand_kernel<<<grid, 256, GEMM_SMEM>>>(res16, Cq16, c2 + q * Kk,
                                                   cmin, ccnt, cidx, cval);
        refine_update_kernel<<<Mm / 8, 256>>>(cmin, ccnt, cidx, cval,
                                              residual, res16, Cq, c2 + q * Kk,
                                              out, out + (size_t)Mm * Dd,
                                              loss + q, q);
    }

    finalize_kernel<<<1, 2 * Qq>>>(out, loss);
}

// round 6
// speedup vs baseline: 4.3983x; 4.3983x over previous
#include <cuda_runtime.h>
#include <cuda_bf16.h>
#include <cstdint>

// Problem constants
#define Bb 8
#define Ss 2048
#define Dd 512
#define Qq 8
#define Kk 1024
#define Mm (Bb * Ss)   // 16384 tokens
#define MARGIN 12.0f

// Scratch (no cudaMalloc allowed)
__device__ float          g_residual[Mm * Dd];   // 32 MB fp32 residual
__device__ __nv_bfloat16  g_res16[Mm * Dd];      // 16 MB bf16 residual
__device__ __nv_bfloat16  g_cb16[Qq * Kk * Dd];  //  8 MB bf16 codebooks
__device__ float          g_dist[Mm * Kk];       // 64 MB approx distances
__device__ float          g_c2[Qq * Kk];
__device__ float          g_loss[Qq];

// ---------------------------------------------------------------------------
// helpers
// ---------------------------------------------------------------------------
__device__ __forceinline__ uint32_t smem_u32(const void* p) {
    uint32_t a;
    asm("{ .reg .u64 t; cvta.to.shared.u64 t, %1; cvt.u32.u64 %0, t; }"
        : "=r"(a) : "l"(p));
    return a;
}
__device__ __forceinline__ void cp16(uint32_t sa, const void* g) {
    asm volatile("cp.async.cg.shared.global [%0], [%1], 16;"
                 :: "r"(sa), "l"(g) : "memory");
}
__device__ __forceinline__ void cp_commit() {
    asm volatile("cp.async.commit_group;" ::: "memory");
}
__device__ __forceinline__ void cp_wait1() {
    asm volatile("cp.async.wait_group 1;" ::: "memory");
}
__device__ __forceinline__ void cp_wait0() {
    asm volatile("cp.async.wait_group 0;" ::: "memory");
}
__device__ __forceinline__ void ldsm4(uint32_t* r, uint32_t addr) {
    asm volatile("ldmatrix.sync.aligned.m8n8.x4.shared.b16 {%0,%1,%2,%3}, [%4];"
                 : "=r"(r[0]), "=r"(r[1]), "=r"(r[2]), "=r"(r[3])
                 : "r"(addr));
}
__device__ __forceinline__ void mma_bf16(float* c, const uint32_t* a,
                                         uint32_t b0, uint32_t b1) {
    asm volatile(
        "mma.sync.aligned.m16n8k16.row.col.f32.bf16.bf16.f32 "
        "{%0,%1,%2,%3}, {%4,%5,%6,%7}, {%8,%9}, {%0,%1,%2,%3};"
        : "+f"(c[0]), "+f"(c[1]), "+f"(c[2]), "+f"(c[3])
        : "r"(a[0]), "r"(a[1]), "r"(a[2]), "r"(a[3]), "r"(b0), "r"(b1));
}

// ---------------------------------------------------------------------------
// init: residual=x (fp32), res16=bf16(x), out=0
// ---------------------------------------------------------------------------
__global__ void init_kernel(const float4* __restrict__ x,
                            float4* __restrict__ residual,
                            __nv_bfloat162* __restrict__ res16,
                            float4* __restrict__ outq, int n4)
{
    int i = blockIdx.x * 256 + threadIdx.x;
    if (i < n4) {
        float4 v = x[i];
        residual[i] = v;
        res16[2 * i]     = __floats2bfloat162_rn(v.x, v.y);
        res16[2 * i + 1] = __floats2bfloat162_rn(v.z, v.w);
        outq[i] = make_float4(0.f, 0.f, 0.f, 0.f);
    }
}

// fp32 -> bf16 codebook convert
__global__ void conv_kernel(const float4* __restrict__ in,
                            __nv_bfloat162* __restrict__ out, int n4)
{
    int i = blockIdx.x * 256 + threadIdx.x;
    if (i < n4) {
        float4 v = in[i];
        out[2 * i]     = __floats2bfloat162_rn(v.x, v.y);
        out[2 * i + 1] = __floats2bfloat162_rn(v.z, v.w);
    }
}

// ---------------------------------------------------------------------------
// c2[q][k] = ||codebook[q][k]||^2  — one warp per row (fp32 exact)
// ---------------------------------------------------------------------------
__global__ void c2_kernel(const float* __restrict__ codebooks, float* __restrict__ c2)
{
    int row  = blockIdx.x * 8 + (threadIdx.x >> 5);
    int lane = threadIdx.x & 31;
    const float4* p = (const float4*)(codebooks + (size_t)row * Dd);
    float s = 0.0f;
    #pragma unroll 4
    for (int i = lane; i < Dd / 4; i += 32) {
        float4 v = p[i];
        s += v.x * v.x + v.y * v.y + v.z * v.z + v.w * v.w;
    }
    #pragma unroll
    for (int off = 16; off; off >>= 1) s += __shfl_down_sync(0xffffffffu, s, off);
    if (lane == 0) c2[row] = s;
}

// ---------------------------------------------------------------------------
// bf16 mma.sync GEMM -> approx distances (PROVEN R3 kernel, unchanged).
// CTA 128x128, BK=64 bf16, double-buffered cp.async, 8 warps of 32x64.
// dist[m][n] = c2[n] - 2 * dot(bf16(r_m), bf16(c_n))
// ---------------------------------------------------------------------------
#define GEMM_SMEM 65536   // 2 bufs * (A 16KB + B 16KB)

__global__ __launch_bounds__(256, 2)
void gemm_dist_kernel(const __nv_bfloat16* __restrict__ A16,
                      const __nv_bfloat16* __restrict__ B16,
                      const float* __restrict__ c2,
                      float* __restrict__ dist)
{
    extern __shared__ char sm[];
    const uint32_t smb   = smem_u32(sm);
    const uint32_t Abase = smb;           // [2][16384]
    const uint32_t Bbase = smb + 32768;   // [2][16384]

    const int tid  = threadIdx.x;
    const int lane = tid & 31;
    const int warp = tid >> 5;
    const int bm = blockIdx.x * 128;
    const int bn = blockIdx.y * 128;
    const int wm = (warp & 3) * 32;
    const int wn = (warp >> 2) * 64;

    const char* gA = (const char*)(A16 + (size_t)bm * Dd);
    const char* gB = (const char*)(B16 + (size_t)bn * Dd);

    float acc[2][8][4];
    #pragma unroll
    for (int mi = 0; mi < 2; ++mi)
        #pragma unroll
        for (int ni = 0; ni < 8; ++ni)
            #pragma unroll
            for (int j = 0; j < 4; ++j) acc[mi][ni][j] = 0.0f;

    #define LOAD_TILE(kt, buf)                                                  \
        {                                                                       \
            _Pragma("unroll")                                                   \
            for (int i = 0; i < 4; ++i) {                                       \
                int u = tid + 256 * i;                                          \
                int row = u >> 3, ch = u & 7;                                   \
                uint32_t so = (uint32_t)(row * 128 + ((ch ^ (row & 7)) * 16));  \
                size_t go = (size_t)row * (Dd * 2) + (kt) * 128 + ch * 16;      \
                cp16(Abase + (buf) * 16384 + so, gA + go);                      \
                cp16(Bbase + (buf) * 16384 + so, gB + go);                      \
            }                                                                   \
            cp_commit();                                                        \
        }

    LOAD_TILE(0, 0);

    for (int kt = 0; kt < 8; ++kt) {
        const int buf = kt & 1;
        if (kt < 7) { LOAD_TILE(kt + 1, buf ^ 1); cp_wait1(); }
        else        { cp_wait0(); }
        __syncthreads();

        #pragma unroll
        for (int s = 0; s < 4; ++s) {
            uint32_t a[2][4], b[4][4];
            const int ch = s * 2 + (lane >> 4);
            #pragma unroll
            for (int mi = 0; mi < 2; ++mi) {
                int row = wm + mi * 16 + (lane & 15);
                ldsm4(a[mi], Abase + buf * 16384 + row * 128 + ((ch ^ (row & 7)) * 16));
            }
            #pragma unroll
            for (int nj = 0; nj < 4; ++nj) {
                int row = wn + nj * 16 + (lane & 15);
                ldsm4(b[nj], Bbase + buf * 16384 + row * 128 + ((ch ^ (row & 7)) * 16));
            }
            #pragma unroll
            for (int mi = 0; mi < 2; ++mi)
                #pragma unroll
                for (int ni = 0; ni < 8; ++ni)
                    mma_bf16(acc[mi][ni], a[mi],
                             b[ni >> 1][ni & 1], b[ni >> 1][(ni & 1) + 2]);
        }
        __syncthreads();
    }

    // epilogue: d = c2[n] - 2*acc, float2 stores
    const int g = lane >> 2, t4 = lane & 3;
    #pragma unroll
    for (int mi = 0; mi < 2; ++mi) {
        const int m0 = bm + wm + mi * 16 + g;
        #pragma unroll
        for (int ni = 0; ni < 8; ++ni) {
            const int n = bn + wn + ni * 8 + 2 * t4;
            float2 cc = *(const float2*)(c2 + n);
            float2 d0, d1;
            d0.x = fmaf(-2.0f, acc[mi][ni][0], cc.x);
            d0.y = fmaf(-2.0f, acc[mi][ni][1], cc.y);
            d1.x = fmaf(-2.0f, acc[mi][ni][2], cc.x);
            d1.y = fmaf(-2.0f, acc[mi][ni][3], cc.y);
            *(float2*)(dist + (size_t)m0 * Kk + n)       = d0;
            *(float2*)(dist + (size_t)(m0 + 8) * Kk + n) = d1;
        }
    }
    #undef LOAD_TILE
}

// ---------------------------------------------------------------------------
// Fused refine + update: warp per token (R3 refine + R3 update in one pass).
// Scan 1024 approx distances, exact-rescore candidates within MARGIN of min
// (fp32 warp dot, residual held in registers), first-index tie-break, then
// residual/res16/out/loss/index update without re-reading the residual.
// ---------------------------------------------------------------------------
__global__ __launch_bounds__(256)
void refine_update_kernel(const float* __restrict__ dist,
                          float* __restrict__ R,
                          __nv_bfloat16* __restrict__ R16w,
                          const float* __restrict__ C,
                          const float* __restrict__ c2,
                          float* __restrict__ outq,
                          float* __restrict__ out_idx,
                          float* __restrict__ loss,
                          int qstage)
{
    const int warp = threadIdx.x >> 5, lane = threadIdx.x & 31;
    const int token = blockIdx.x * 8 + warp;

    // scan approx distances (coalesced float4)
    const float4* dp = (const float4*)(dist + (size_t)token * Kk);
    float v[32];
    float vmin = 3.4e38f;
    #pragma unroll
    for (int i = 0; i < 8; ++i) {
        float4 f = dp[lane + 32 * i];
        v[4 * i] = f.x; v[4 * i + 1] = f.y; v[4 * i + 2] = f.z; v[4 * i + 3] = f.w;
        vmin = fminf(vmin, fminf(fminf(f.x, f.y), fminf(f.z, f.w)));
    }
    #pragma unroll
    for (int o = 16; o; o >>= 1) vmin = fminf(vmin, __shfl_xor_sync(~0u, vmin, o));

    const float thresh = vmin + MARGIN;
    unsigned mask = 0;
    #pragma unroll
    for (int s = 0; s < 32; ++s)
        if (v[s] <= thresh) mask |= 1u << s;

    // residual in registers (used by rescore AND update)
    const float4* rrp = (const float4*)(R + (size_t)token * Dd);
    float4 rr[4];
    #pragma unroll
    for (int j = 0; j < 4; ++j) rr[j] = rrp[lane + 32 * j];

    float bd = 3.4e38f;
    int   bn = 1 << 30;

    while (true) {
        unsigned has = __ballot_sync(~0u, mask != 0);
        if (!has) break;
        int leader = __ffs(has) - 1;
        int s = 0;
        if (lane == leader) { s = __ffs(mask) - 1; mask &= mask - 1; }
        s = __shfl_sync(~0u, s, leader);
        const int n = 128 * (s >> 2) + 4 * leader + (s & 3);

        const float4* cc4 = (const float4*)(C + (size_t)n * Dd);
        float ssum = 0.0f;
        #pragma unroll
        for (int t = 0; t < 4; ++t) {
            float4 b = cc4[lane + 32 * t];
            ssum += rr[t].x * b.x + rr[t].y * b.y + rr[t].z * b.z + rr[t].w * b.w;
        }
        #pragma unroll
        for (int o = 16; o; o >>= 1) ssum += __shfl_xor_sync(~0u, ssum, o);

        float d = fmaf(-2.0f, ssum, __ldg(c2 + n));
        if (d < bd || (d == bd && n < bn)) { bd = d; bn = n; }
    }

    // fused update (residual already in rr)
    const float4* cp = (const float4*)(C + (size_t)bn * Dd);
    float4* rp = (float4*)(R + (size_t)token * Dd);
    float4* op = (float4*)(outq + (size_t)token * Dd);
    __nv_bfloat162* r16p = (__nv_bfloat162*)(R16w + (size_t)token * Dd);
    float lsum = 0.0f;
    #pragma unroll
    for (int j = 0; j < 4; ++j) {
        float4 cv = cp[lane + 32 * j];
        float4 nr = make_float4(rr[j].x - cv.x, rr[j].y - cv.y,
                                rr[j].z - cv.z, rr[j].w - cv.w);
        rp[lane + 32 * j] = nr;
        r16p[2 * (lane + 32 * j)]     = __floats2bfloat162_rn(nr.x, nr.y);
        r16p[2 * (lane + 32 * j) + 1] = __floats2bfloat162_rn(nr.z, nr.w);
        float4 ov = op[lane + 32 * j];
        op[lane + 32 * j] = make_float4(ov.x + cv.x, ov.y + cv.y,
                                        ov.z + cv.z, ov.w + cv.w);
        lsum += nr.x * nr.x + nr.y * nr.y + nr.z * nr.z + nr.w * nr.w;
    }
    #pragma unroll
    for (int o = 16; o; o >>= 1) lsum += __shfl_xor_sync(~0u, lsum, o);
    if (lane == 0) {
        out_idx[(size_t)token * Qq + qstage] = (float)bn;
        atomicAdd(loss, lsum);
    }
}

// ---------------------------------------------------------------------------
// Tail outputs: all_expired (zeros) then all_losses (mean over B*S*D)
// ---------------------------------------------------------------------------
__global__ void finalize_kernel(float* __restrict__ out, const float* __restrict__ loss)
{
    const size_t base = (size_t)Mm * Dd + (size_t)Mm * Qq;
    int t = threadIdx.x;
    if (t < Qq)
        out[base + t] = 0.0f;
    else if (t < 2 * Qq)
        out[base + Qq + (t - Qq)] = loss[t - Qq] * (1.0f / ((float)Mm * (float)Dd));
}

// ---------------------------------------------------------------------------
extern "C" void kernel_launch(void* const* d_in, const int* in_sizes, int n_in,
                              void* d_out, int out_size)
{
    const float* x  = (const float*)d_in[0];   // [B,S,D] f32
    const float* cb = (const float*)d_in[1];   // [Q,K,D] f32
    float* out = (float*)d_out;

    float* residual;         cudaGetSymbolAddress((void**)&residual, g_residual);
    __nv_bfloat16* res16;    cudaGetSymbolAddress((void**)&res16,    g_res16);
    __nv_bfloat16* cb16;     cudaGetSymbolAddress((void**)&cb16,     g_cb16);
    float* dist;             cudaGetSymbolAddress((void**)&dist,     g_dist);
    float* c2;               cudaGetSymbolAddress((void**)&c2,       g_c2);
    float* loss;             cudaGetSymbolAddress((void**)&loss,     g_loss);

    cudaFuncSetAttribute(gemm_dist_kernel,
                         cudaFuncAttributeMaxDynamicSharedMemorySize, GEMM_SMEM);

    cudaMemsetAsync(loss, 0, Qq * sizeof(float));

    init_kernel<<<Mm * Dd / 4 / 256, 256>>>((const float4*)x, (float4*)residual,
                                            (__nv_bfloat162*)res16, (float4*)out,
                                            Mm * Dd / 4);
    conv_kernel<<<(Qq * Kk * Dd / 4 + 255) / 256, 256>>>((const float4*)cb,
                                                         (__nv_bfloat162*)cb16,
                                                         Qq * Kk * Dd / 4);
    c2_kernel<<<Qq * Kk / 8, 256>>>(cb, c2);

    for (int q = 0; q < Qq; ++q) {
        const float* Cq = cb + (size_t)q * Kk * Dd;
        const __nv_bfloat16* Cq16 = cb16 + (size_t)q * Kk * Dd;
        dim3 grid(Mm / 128, Kk / 128);
        gemm_dist_kernel<<<grid, 256, GEMM_SMEM>>>(res16, Cq16, c2 + q * Kk, dist);
        refine_update_kernel<<<Mm / 8, 256>>>(dist, residual, res16, Cq,
                                              c2 + q * Kk, out,
                                              out + (size_t)Mm * Dd, loss + q, q);
    }

    finalize_kernel<<<1, 2 * Qq>>>(out, loss);
}

// round 7
// speedup vs baseline: 4.8349x; 1.0993x over previous
#include <cuda_runtime.h>
#include <cuda_bf16.h>
#include <cuda_fp16.h>
#include <cstdint>

// Problem constants
#define Bb 8
#define Ss 2048
#define Dd 512
#define Qq 8
#define Kk 1024
#define Mm (Bb * Ss)   // 16384 tokens
#define MARGIN 14.0f

// Scratch (no cudaMalloc allowed)
__device__ float          g_residual[Mm * Dd];   // 32 MB fp32 residual
__device__ __nv_bfloat16  g_res16[Mm * Dd];      // 16 MB bf16 residual
__device__ __nv_bfloat16  g_cb16[Qq * Kk * Dd];  //  8 MB bf16 codebooks
__device__ __half         g_dist[Mm * Kk];       // 32 MB approx distances (fp16)
__device__ float          g_c2[Qq * Kk];
__device__ float          g_loss[Qq];

// ---------------------------------------------------------------------------
// helpers
// ---------------------------------------------------------------------------
__device__ __forceinline__ uint32_t smem_u32(const void* p) {
    uint32_t a;
    asm("{ .reg .u64 t; cvta.to.shared.u64 t, %1; cvt.u32.u64 %0, t; }"
        : "=r"(a) : "l"(p));
    return a;
}
__device__ __forceinline__ void cp16(uint32_t sa, const void* g) {
    asm volatile("cp.async.cg.shared.global [%0], [%1], 16;"
                 :: "r"(sa), "l"(g) : "memory");
}
__device__ __forceinline__ void cp_commit() {
    asm volatile("cp.async.commit_group;" ::: "memory");
}
__device__ __forceinline__ void cp_wait1() {
    asm volatile("cp.async.wait_group 1;" ::: "memory");
}
__device__ __forceinline__ void cp_wait0() {
    asm volatile("cp.async.wait_group 0;" ::: "memory");
}
__device__ __forceinline__ void ldsm4(uint32_t* r, uint32_t addr) {
    asm volatile("ldmatrix.sync.aligned.m8n8.x4.shared.b16 {%0,%1,%2,%3}, [%4];"
                 : "=r"(r[0]), "=r"(r[1]), "=r"(r[2]), "=r"(r[3])
                 : "r"(addr));
}
__device__ __forceinline__ void mma_bf16(float* c, const uint32_t* a,
                                         uint32_t b0, uint32_t b1) {
    asm volatile(
        "mma.sync.aligned.m16n8k16.row.col.f32.bf16.bf16.f32 "
        "{%0,%1,%2,%3}, {%4,%5,%6,%7}, {%8,%9}, {%0,%1,%2,%3};"
        : "+f"(c[0]), "+f"(c[1]), "+f"(c[2]), "+f"(c[3])
        : "r"(a[0]), "r"(a[1]), "r"(a[2]), "r"(a[3]), "r"(b0), "r"(b1));
}

// ---------------------------------------------------------------------------
// init: residual=x (fp32), res16=bf16(x)   (no out zeroing needed anymore)
// ---------------------------------------------------------------------------
__global__ void init_kernel(const float4* __restrict__ x,
                            float4* __restrict__ residual,
                            __nv_bfloat162* __restrict__ res16, int n4)
{
    int i = blockIdx.x * 256 + threadIdx.x;
    if (i < n4) {
        float4 v = x[i];
        residual[i] = v;
        res16[2 * i]     = __floats2bfloat162_rn(v.x, v.y);
        res16[2 * i + 1] = __floats2bfloat162_rn(v.z, v.w);
    }
}

// fp32 -> bf16 codebook convert
__global__ void conv_kernel(const float4* __restrict__ in,
                            __nv_bfloat162* __restrict__ out, int n4)
{
    int i = blockIdx.x * 256 + threadIdx.x;
    if (i < n4) {
        float4 v = in[i];
        out[2 * i]     = __floats2bfloat162_rn(v.x, v.y);
        out[2 * i + 1] = __floats2bfloat162_rn(v.z, v.w);
    }
}

// ---------------------------------------------------------------------------
// c2[q][k] = ||codebook[q][k]||^2  — one warp per row (fp32 exact)
// ---------------------------------------------------------------------------
__global__ void c2_kernel(const float* __restrict__ codebooks, float* __restrict__ c2)
{
    int row  = blockIdx.x * 8 + (threadIdx.x >> 5);
    int lane = threadIdx.x & 31;
    const float4* p = (const float4*)(codebooks + (size_t)row * Dd);
    float s = 0.0f;
    #pragma unroll 4
    for (int i = lane; i < Dd / 4; i += 32) {
        float4 v = p[i];
        s += v.x * v.x + v.y * v.y + v.z * v.z + v.w * v.w;
    }
    #pragma unroll
    for (int off = 16; off; off >>= 1) s += __shfl_down_sync(0xffffffffu, s, off);
    if (lane == 0) c2[row] = s;
}

// ---------------------------------------------------------------------------
// bf16 mma.sync GEMM -> approx distances (fp16 stores).
// CTA 128x128, BK=64 bf16, double-buffered cp.async, 8 warps of 32x64.
// dist[m][n] = fp16( c2[n] - 2 * dot(bf16(r_m), bf16(c_n)) )
// ---------------------------------------------------------------------------
#define GEMM_SMEM 65536   // 2 bufs * (A 16KB + B 16KB)

__global__ __launch_bounds__(256, 2)
void gemm_dist_kernel(const __nv_bfloat16* __restrict__ A16,
                      const __nv_bfloat16* __restrict__ B16,
                      const float* __restrict__ c2,
                      __half* __restrict__ dist)
{
    extern __shared__ char sm[];
    const uint32_t smb   = smem_u32(sm);
    const uint32_t Abase = smb;           // [2][16384]
    const uint32_t Bbase = smb + 32768;   // [2][16384]

    const int tid  = threadIdx.x;
    const int lane = tid & 31;
    const int warp = tid >> 5;
    const int bm = blockIdx.x * 128;
    const int bn = blockIdx.y * 128;
    const int wm = (warp & 3) * 32;
    const int wn = (warp >> 2) * 64;

    const char* gA = (const char*)(A16 + (size_t)bm * Dd);
    const char* gB = (const char*)(B16 + (size_t)bn * Dd);

    float acc[2][8][4];
    #pragma unroll
    for (int mi = 0; mi < 2; ++mi)
        #pragma unroll
        for (int ni = 0; ni < 8; ++ni)
            #pragma unroll
            for (int j = 0; j < 4; ++j) acc[mi][ni][j] = 0.0f;

    #define LOAD_TILE(kt, buf)                                                  \
        {                                                                       \
            _Pragma("unroll")                                                   \
            for (int i = 0; i < 4; ++i) {                                       \
                int u = tid + 256 * i;                                          \
                int row = u >> 3, ch = u & 7;                                   \
                uint32_t so = (uint32_t)(row * 128 + ((ch ^ (row & 7)) * 16));  \
                size_t go = (size_t)row * (Dd * 2) + (kt) * 128 + ch * 16;      \
                cp16(Abase + (buf) * 16384 + so, gA + go);                      \
                cp16(Bbase + (buf) * 16384 + so, gB + go);                      \
            }                                                                   \
            cp_commit();                                                        \
        }

    LOAD_TILE(0, 0);

    for (int kt = 0; kt < 8; ++kt) {
        const int buf = kt & 1;
        if (kt < 7) { LOAD_TILE(kt + 1, buf ^ 1); cp_wait1(); }
        else        { cp_wait0(); }
        __syncthreads();

        #pragma unroll
        for (int s = 0; s < 4; ++s) {
            uint32_t a[2][4], b[4][4];
            const int ch = s * 2 + (lane >> 4);
            #pragma unroll
            for (int mi = 0; mi < 2; ++mi) {
                int row = wm + mi * 16 + (lane & 15);
                ldsm4(a[mi], Abase + buf * 16384 + row * 128 + ((ch ^ (row & 7)) * 16));
            }
            #pragma unroll
            for (int nj = 0; nj < 4; ++nj) {
                int row = wn + nj * 16 + (lane & 15);
                ldsm4(b[nj], Bbase + buf * 16384 + row * 128 + ((ch ^ (row & 7)) * 16));
            }
            #pragma unroll
            for (int mi = 0; mi < 2; ++mi)
                #pragma unroll
                for (int ni = 0; ni < 8; ++ni)
                    mma_bf16(acc[mi][ni], a[mi],
                             b[ni >> 1][ni & 1], b[ni >> 1][(ni & 1) + 2]);
        }
        __syncthreads();
    }

    // epilogue: d = c2[n] - 2*acc, fp16 stores (half2, 4B per lane-quad slot)
    const int g = lane >> 2, t4 = lane & 3;
    #pragma unroll
    for (int mi = 0; mi < 2; ++mi) {
        const int m0 = bm + wm + mi * 16 + g;
        #pragma unroll
        for (int ni = 0; ni < 8; ++ni) {
            const int n = bn + wn + ni * 8 + 2 * t4;
            float2 cc = *(const float2*)(c2 + n);
            __half2 h0 = __floats2half2_rn(fmaf(-2.0f, acc[mi][ni][0], cc.x),
                                           fmaf(-2.0f, acc[mi][ni][1], cc.y));
            __half2 h1 = __floats2half2_rn(fmaf(-2.0f, acc[mi][ni][2], cc.x),
                                           fmaf(-2.0f, acc[mi][ni][3], cc.y));
            *(__half2*)(dist + (size_t)m0 * Kk + n)       = h0;
            *(__half2*)(dist + (size_t)(m0 + 8) * Kk + n) = h1;
        }
    }
    #undef LOAD_TILE
}

// ---------------------------------------------------------------------------
// Fused refine + update: warp per token.
// Scan 1024 fp16 approx distances, exact-rescore candidates within MARGIN of
// min (fp32 warp dot, residual held in registers), first-index tie-break,
// then residual/res16/loss/index update. NO quantized accumulation here
// (out = x - residual_final, done once at the end).
// ---------------------------------------------------------------------------
__global__ __launch_bounds__(256)
void refine_update_kernel(const __half* __restrict__ dist,
                          float* __restrict__ R,
                          __nv_bfloat16* __restrict__ R16w,
                          const float* __restrict__ C,
                          const float* __restrict__ c2,
                          float* __restrict__ out_idx,
                          float* __restrict__ loss,
                          int qstage)
{
    const int warp = threadIdx.x >> 5, lane = threadIdx.x & 31;
    const int token = blockIdx.x * 8 + warp;

    // scan fp16 distances: 4 x uint4 per lane = 32 halves
    const uint4* dp = (const uint4*)(dist + (size_t)token * Kk);
    float v[32];
    float vmin = 3.4e38f;
    #pragma unroll
    for (int i = 0; i < 4; ++i) {
        uint4 u = dp[lane + 32 * i];
        const __half2* hp = (const __half2*)&u;
        #pragma unroll
        for (int p = 0; p < 4; ++p) {
            float2 f = __half22float2(hp[p]);
            v[8 * i + 2 * p]     = f.x;
            v[8 * i + 2 * p + 1] = f.y;
            vmin = fminf(vmin, fminf(f.x, f.y));
        }
    }
    #pragma unroll
    for (int o = 16; o; o >>= 1) vmin = fminf(vmin, __shfl_xor_sync(~0u, vmin, o));

    const float thresh = vmin + MARGIN;
    unsigned mask = 0;
    #pragma unroll
    for (int s = 0; s < 32; ++s)
        if (v[s] <= thresh) mask |= 1u << s;

    // residual in registers (used by rescore AND update)
    const float4* rrp = (const float4*)(R + (size_t)token * Dd);
    float4 rr[4];
    #pragma unroll
    for (int j = 0; j < 4; ++j) rr[j] = rrp[lane + 32 * j];

    float bd = 3.4e38f;
    int   bn = 1 << 30;

    while (true) {
        unsigned has = __ballot_sync(~0u, mask != 0);
        if (!has) break;
        int leader = __ffs(has) - 1;
        int s = 0;
        if (lane == leader) { s = __ffs(mask) - 1; mask &= mask - 1; }
        s = __shfl_sync(~0u, s, leader);
        // value v[s] of lane `leader` is code n = 8*(leader + 32*(s>>3)) + (s&7)
        const int n = 8 * (leader + 32 * (s >> 3)) + (s & 7);

        const float4* cc4 = (const float4*)(C + (size_t)n * Dd);
        float ssum = 0.0f;
        #pragma unroll
        for (int t = 0; t < 4; ++t) {
            float4 b = cc4[lane + 32 * t];
            ssum += rr[t].x * b.x + rr[t].y * b.y + rr[t].z * b.z + rr[t].w * b.w;
        }
        #pragma unroll
        for (int o = 16; o; o >>= 1) ssum += __shfl_xor_sync(~0u, ssum, o);

        float d = fmaf(-2.0f, ssum, __ldg(c2 + n));
        if (d < bd || (d == bd && n < bn)) { bd = d; bn = n; }
    }

    // fused update (residual already in rr)
    const float4* cp = (const float4*)(C + (size_t)bn * Dd);
    float4* rp = (float4*)(R + (size_t)token * Dd);
    __nv_bfloat162* r16p = (__nv_bfloat162*)(R16w + (size_t)token * Dd);
    float lsum = 0.0f;
    #pragma unroll
    for (int j = 0; j < 4; ++j) {
        float4 cv = cp[lane + 32 * j];
        float4 nr = make_float4(rr[j].x - cv.x, rr[j].y - cv.y,
                                rr[j].z - cv.z, rr[j].w - cv.w);
        rp[lane + 32 * j] = nr;
        r16p[2 * (lane + 32 * j)]     = __floats2bfloat162_rn(nr.x, nr.y);
        r16p[2 * (lane + 32 * j) + 1] = __floats2bfloat162_rn(nr.z, nr.w);
        lsum += nr.x * nr.x + nr.y * nr.y + nr.z * nr.z + nr.w * nr.w;
    }
    #pragma unroll
    for (int o = 16; o; o >>= 1) lsum += __shfl_xor_sync(~0u, lsum, o);
    if (lane == 0) {
        out_idx[(size_t)token * Qq + qstage] = (float)bn;
        atomicAdd(loss, lsum);
    }
}

// ---------------------------------------------------------------------------
// Final: quantized_out = x - residual_final  (one pass)
// ---------------------------------------------------------------------------
__global__ void final_out_kernel(const float4* __restrict__ x,
                                 const float4* __restrict__ residual,
                                 float4* __restrict__ out, int n4)
{
    int i = blockIdx.x * 256 + threadIdx.x;
    if (i < n4) {
        float4 a = x[i], r = residual[i];
        out[i] = make_float4(a.x - r.x, a.y - r.y, a.z - r.z, a.w - r.w);
    }
}

// Tail outputs: all_expired (zeros) then all_losses (mean over B*S*D)
__global__ void finalize_kernel(float* __restrict__ out, const float* __restrict__ loss)
{
    const size_t base = (size_t)Mm * Dd + (size_t)Mm * Qq;
    int t = threadIdx.x;
    if (t < Qq)
        out[base + t] = 0.0f;
    else if (t < 2 * Qq)
        out[base + Qq + (t - Qq)] = loss[t - Qq] * (1.0f / ((float)Mm * (float)Dd));
}

// ---------------------------------------------------------------------------
extern "C" void kernel_launch(void* const* d_in, const int* in_sizes, int n_in,
                              void* d_out, int out_size)
{
    const float* x  = (const float*)d_in[0];   // [B,S,D] f32
    const float* cb = (const float*)d_in[1];   // [Q,K,D] f32
    float* out = (float*)d_out;

    float* residual;         cudaGetSymbolAddress((void**)&residual, g_residual);
    __nv_bfloat16* res16;    cudaGetSymbolAddress((void**)&res16,    g_res16);
    __nv_bfloat16* cb16;     cudaGetSymbolAddress((void**)&cb16,     g_cb16);
    __half* dist;            cudaGetSymbolAddress((void**)&dist,     g_dist);
    float* c2;               cudaGetSymbolAddress((void**)&c2,       g_c2);
    float* loss;             cudaGetSymbolAddress((void**)&loss,     g_loss);

    cudaFuncSetAttribute(gemm_dist_kernel,
                         cudaFuncAttributeMaxDynamicSharedMemorySize, GEMM_SMEM);

    cudaMemsetAsync(loss, 0, Qq * sizeof(float));

    init_kernel<<<Mm * Dd / 4 / 256, 256>>>((const float4*)x, (float4*)residual,
                                            (__nv_bfloat162*)res16, Mm * Dd / 4);
    conv_kernel<<<(Qq * Kk * Dd / 4 + 255) / 256, 256>>>((const float4*)cb,
                                                         (__nv_bfloat162*)cb16,
                                                         Qq * Kk * Dd / 4);
    c2_kernel<<<Qq * Kk / 8, 256>>>(cb, c2);

    for (int q = 0; q < Qq; ++q) {
        const float* Cq = cb + (size_t)q * Kk * Dd;
        const __nv_bfloat16* Cq16 = cb16 + (size_t)q * Kk * Dd;
        dim3 grid(Mm / 128, Kk / 128);
        gemm_dist_kernel<<<grid, 256, GEMM_SMEM>>>(res16, Cq16, c2 + q * Kk, dist);
        refine_update_kernel<<<Mm / 8, 256>>>(dist, residual, res16, Cq,
                                              c2 + q * Kk,
                                              out + (size_t)Mm * Dd, loss + q, q);
    }

    final_out_kernel<<<Mm * Dd / 4 / 256, 256>>>((const float4*)x,
                                                 (const float4*)residual,
                                                 (float4*)out, Mm * Dd / 4);
    finalize_kernel<<<1, 2 * Qq>>>(out, loss);
}

// round 8
// speedup vs baseline: 4.9827x; 1.0306x over previous
#include <cuda_runtime.h>
#include <cuda_fp16.h>
#include <cstdint>

// Problem constants
#define Bb 8
#define Ss 2048
#define Dd 512
#define Qq 8
#define Kk 1024
#define Mm (Bb * Ss)   // 16384 tokens
#define MARGIN 8.0f

// Scratch (no cudaMalloc allowed)
__device__ float   g_residual[Mm * Dd];   // 32 MB fp32 residual
__device__ __half  g_res16[Mm * Dd];      // 16 MB fp16 residual
__device__ __half  g_cb16[Qq * Kk * Dd];  //  8 MB fp16 codebooks
__device__ __half  g_dist[Mm * Kk];       // 32 MB approx distances (fp16)
__device__ float   g_c2[Qq * Kk];
__device__ float   g_loss[Qq];

// ---------------------------------------------------------------------------
// helpers
// ---------------------------------------------------------------------------
__device__ __forceinline__ uint32_t smem_u32(const void* p) {
    uint32_t a;
    asm("{ .reg .u64 t; cvta.to.shared.u64 t, %1; cvt.u32.u64 %0, t; }"
        : "=r"(a) : "l"(p));
    return a;
}
__device__ __forceinline__ void cp16(uint32_t sa, const void* g) {
    asm volatile("cp.async.cg.shared.global [%0], [%1], 16;"
                 :: "r"(sa), "l"(g) : "memory");
}
__device__ __forceinline__ void cp_commit() {
    asm volatile("cp.async.commit_group;" ::: "memory");
}
__device__ __forceinline__ void cp_wait0() {
    asm volatile("cp.async.wait_group 0;" ::: "memory");
}
__device__ __forceinline__ void ldsm4(uint32_t* r, uint32_t addr) {
    asm volatile("ldmatrix.sync.aligned.m8n8.x4.shared.b16 {%0,%1,%2,%3}, [%4];"
                 : "=r"(r[0]), "=r"(r[1]), "=r"(r[2]), "=r"(r[3])
                 : "r"(addr));
}
// fp16 inputs, fp16 accumulators (2 x b32 regs hold 4 halves)
__device__ __forceinline__ void mma_f16acc(uint32_t* c, const uint32_t* a,
                                           uint32_t b0, uint32_t b1) {
    asm volatile(
        "mma.sync.aligned.m16n8k16.row.col.f16.f16.f16.f16 "
        "{%0,%1}, {%2,%3,%4,%5}, {%6,%7}, {%0,%1};"
        : "+r"(c[0]), "+r"(c[1])
        : "r"(a[0]), "r"(a[1]), "r"(a[2]), "r"(a[3]), "r"(b0), "r"(b1));
}

// ---------------------------------------------------------------------------
// init: residual=x (fp32), res16=fp16(x)
// ---------------------------------------------------------------------------
__global__ void init_kernel(const float4* __restrict__ x,
                            float4* __restrict__ residual,
                            __half2* __restrict__ res16, int n4)
{
    int i = blockIdx.x * 256 + threadIdx.x;
    if (i < n4) {
        float4 v = x[i];
        residual[i] = v;
        res16[2 * i]     = __floats2half2_rn(v.x, v.y);
        res16[2 * i + 1] = __floats2half2_rn(v.z, v.w);
    }
}

// fp32 -> fp16 codebook convert
__global__ void conv_kernel(const float4* __restrict__ in,
                            __half2* __restrict__ out, int n4)
{
    int i = blockIdx.x * 256 + threadIdx.x;
    if (i < n4) {
        float4 v = in[i];
        out[2 * i]     = __floats2half2_rn(v.x, v.y);
        out[2 * i + 1] = __floats2half2_rn(v.z, v.w);
    }
}

// ---------------------------------------------------------------------------
// c2[q][k] = ||codebook[q][k]||^2  — one warp per row (fp32 exact)
// ---------------------------------------------------------------------------
__global__ void c2_kernel(const float* __restrict__ codebooks, float* __restrict__ c2)
{
    int row  = blockIdx.x * 8 + (threadIdx.x >> 5);
    int lane = threadIdx.x & 31;
    const float4* p = (const float4*)(codebooks + (size_t)row * Dd);
    float s = 0.0f;
    #pragma unroll 4
    for (int i = lane; i < Dd / 4; i += 32) {
        float4 v = p[i];
        s += v.x * v.x + v.y * v.y + v.z * v.z + v.w * v.w;
    }
    #pragma unroll
    for (int off = 16; off; off >>= 1) s += __shfl_down_sync(0xffffffffu, s, off);
    if (lane == 0) c2[row] = s;
}

// ---------------------------------------------------------------------------
// fp16 mma.sync GEMM (fp16 acc) -> approx distances (fp16 stores).
// CTA 128x128, BK=64, double-buffered cp.async with ONE sync per k-tile,
// 8 warps of 32x64.  dist[m][n] = fp16( c2[n] - 2 * dot(h(r_m), h(c_n)) )
// ---------------------------------------------------------------------------
#define GEMM_SMEM 65536   // 2 bufs * (A 16KB + B 16KB)

__global__ __launch_bounds__(256, 2)
void gemm_dist_kernel(const __half* __restrict__ A16,
                      const __half* __restrict__ B16,
                      const float* __restrict__ c2,
                      __half* __restrict__ dist)
{
    extern __shared__ char sm[];
    const uint32_t smb   = smem_u32(sm);
    const uint32_t Abase = smb;           // [2][16384]
    const uint32_t Bbase = smb + 32768;   // [2][16384]

    const int tid  = threadIdx.x;
    const int lane = tid & 31;
    const int warp = tid >> 5;
    const int bm = blockIdx.x * 128;
    const int bn = blockIdx.y * 128;
    const int wm = (warp & 3) * 32;
    const int wn = (warp >> 2) * 64;

    const char* gA = (const char*)(A16 + (size_t)bm * Dd);
    const char* gB = (const char*)(B16 + (size_t)bn * Dd);

    uint32_t acc[2][8][2];
    #pragma unroll
    for (int mi = 0; mi < 2; ++mi)
        #pragma unroll
        for (int ni = 0; ni < 8; ++ni) { acc[mi][ni][0] = 0u; acc[mi][ni][1] = 0u; }

    #define LOAD_TILE(kt, buf)                                                  \
        {                                                                       \
            _Pragma("unroll")                                                   \
            for (int i = 0; i < 4; ++i) {                                       \
                int u = tid + 256 * i;                                          \
                int row = u >> 3, ch = u & 7;                                   \
                uint32_t so = (uint32_t)(row * 128 + ((ch ^ (row & 7)) * 16));  \
                size_t go = (size_t)row * (Dd * 2) + (kt) * 128 + ch * 16;      \
                cp16(Abase + (buf) * 16384 + so, gA + go);                      \
                cp16(Bbase + (buf) * 16384 + so, gB + go);                      \
            }                                                                   \
            cp_commit();                                                        \
        }

    LOAD_TILE(0, 0);

    for (int kt = 0; kt < 8; ++kt) {
        const int buf = kt & 1;
        cp_wait0();            // own g(kt) loads done
        __syncthreads();       // everyone's g(kt) visible AND compute kt-1 done
        if (kt < 7) LOAD_TILE(kt + 1, buf ^ 1);   // overlaps with compute below

        #pragma unroll
        for (int s = 0; s < 4; ++s) {
            uint32_t a[2][4], b[4][4];
            const int ch = s * 2 + (lane >> 4);
            #pragma unroll
            for (int mi = 0; mi < 2; ++mi) {
                int row = wm + mi * 16 + (lane & 15);
                ldsm4(a[mi], Abase + buf * 16384 + row * 128 + ((ch ^ (row & 7)) * 16));
            }
            #pragma unroll
            for (int nj = 0; nj < 4; ++nj) {
                int row = wn + nj * 16 + (lane & 15);
                ldsm4(b[nj], Bbase + buf * 16384 + row * 128 + ((ch ^ (row & 7)) * 16));
            }
            #pragma unroll
            for (int mi = 0; mi < 2; ++mi)
                #pragma unroll
                for (int ni = 0; ni < 8; ++ni)
                    mma_f16acc(acc[mi][ni], a[mi],
                               b[ni >> 1][ni & 1], b[ni >> 1][(ni & 1) + 2]);
        }
    }

    // epilogue: d = c2[n] - 2*acc (acc fp16 -> fp32), fp16 stores
    const int g = lane >> 2, t4 = lane & 3;
    #pragma unroll
    for (int mi = 0; mi < 2; ++mi) {
        const int m0 = bm + wm + mi * 16 + g;
        #pragma unroll
        for (int ni = 0; ni < 8; ++ni) {
            const int n = bn + wn + ni * 8 + 2 * t4;
            float2 cc = *(const float2*)(c2 + n);
            float2 f0 = __half22float2(*(__half2*)&acc[mi][ni][0]);  // rows m0
            float2 f1 = __half22float2(*(__half2*)&acc[mi][ni][1]);  // rows m0+8
            __half2 h0 = __floats2half2_rn(fmaf(-2.0f, f0.x, cc.x),
                                           fmaf(-2.0f, f0.y, cc.y));
            __half2 h1 = __floats2half2_rn(fmaf(-2.0f, f1.x, cc.x),
                                           fmaf(-2.0f, f1.y, cc.y));
            *(__half2*)(dist + (size_t)m0 * Kk + n)       = h0;
            *(__half2*)(dist + (size_t)(m0 + 8) * Kk + n) = h1;
        }
    }
    #undef LOAD_TILE
}

// ---------------------------------------------------------------------------
// Fused refine + update: warp per token.
// Scan 1024 fp16 approx distances, exact-rescore candidates within MARGIN of
// min (fp32 warp dot, residual held in registers), first-index tie-break,
// then residual/res16/loss/index update. out = x - residual_final at the end.
// ---------------------------------------------------------------------------
__global__ __launch_bounds__(256)
void refine_update_kernel(const __half* __restrict__ dist,
                          float* __restrict__ R,
                          __half* __restrict__ R16w,
                          const float* __restrict__ C,
                          const float* __restrict__ c2,
                          float* __restrict__ out_idx,
                          float* __restrict__ loss,
                          int qstage)
{
    const int warp = threadIdx.x >> 5, lane = threadIdx.x & 31;
    const int token = blockIdx.x * 8 + warp;

    // scan fp16 distances: 4 x uint4 per lane = 32 halves
    const uint4* dp = (const uint4*)(dist + (size_t)token * Kk);
    float v[32];
    float vmin = 3.4e38f;
    #pragma unroll
    for (int i = 0; i < 4; ++i) {
        uint4 u = dp[lane + 32 * i];
        const __half2* hp = (const __half2*)&u;
        #pragma unroll
        for (int p = 0; p < 4; ++p) {
            float2 f = __half22float2(hp[p]);
            v[8 * i + 2 * p]     = f.x;
            v[8 * i + 2 * p + 1] = f.y;
            vmin = fminf(vmin, fminf(f.x, f.y));
        }
    }
    #pragma unroll
    for (int o = 16; o; o >>= 1) vmin = fminf(vmin, __shfl_xor_sync(~0u, vmin, o));

    const float thresh = vmin + MARGIN;
    unsigned mask = 0;
    #pragma unroll
    for (int s = 0; s < 32; ++s)
        if (v[s] <= thresh) mask |= 1u << s;

    // residual in registers (used by rescore AND update)
    const float4* rrp = (const float4*)(R + (size_t)token * Dd);
    float4 rr[4];
    #pragma unroll
    for (int j = 0; j < 4; ++j) rr[j] = rrp[lane + 32 * j];

    float bd = 3.4e38f;
    int   bn = 1 << 30;

    while (true) {
        unsigned has = __ballot_sync(~0u, mask != 0);
        if (!has) break;
        int leader = __ffs(has) - 1;
        int s = 0;
        if (lane == leader) { s = __ffs(mask) - 1; mask &= mask - 1; }
        s = __shfl_sync(~0u, s, leader);
        // value v[s] of lane `leader` is code n = 8*(leader + 32*(s>>3)) + (s&7)
        const int n = 8 * (leader + 32 * (s >> 3)) + (s & 7);

        const float4* cc4 = (const float4*)(C + (size_t)n * Dd);
        float ssum = 0.0f;
        #pragma unroll
        for (int t = 0; t < 4; ++t) {
            float4 b = cc4[lane + 32 * t];
            ssum += rr[t].x * b.x + rr[t].y * b.y + rr[t].z * b.z + rr[t].w * b.w;
        }
        #pragma unroll
        for (int o = 16; o; o >>= 1) ssum += __shfl_xor_sync(~0u, ssum, o);

        float d = fmaf(-2.0f, ssum, __ldg(c2 + n));
        if (d < bd || (d == bd && n < bn)) { bd = d; bn = n; }
    }

    // fused update (residual already in rr)
    const float4* cp = (const float4*)(C + (size_t)bn * Dd);
    float4* rp = (float4*)(R + (size_t)token * Dd);
    __half2* r16p = (__half2*)(R16w + (size_t)token * Dd);
    float lsum = 0.0f;
    #pragma unroll
    for (int j = 0; j < 4; ++j) {
        float4 cv = cp[lane + 32 * j];
        float4 nr = make_float4(rr[j].x - cv.x, rr[j].y - cv.y,
                                rr[j].z - cv.z, rr[j].w - cv.w);
        rp[lane + 32 * j] = nr;
        r16p[2 * (lane + 32 * j)]     = __floats2half2_rn(nr.x, nr.y);
        r16p[2 * (lane + 32 * j) + 1] = __floats2half2_rn(nr.z, nr.w);
        lsum += nr.x * nr.x + nr.y * nr.y + nr.z * nr.z + nr.w * nr.w;
    }
    #pragma unroll
    for (int o = 16; o; o >>= 1) lsum += __shfl_xor_sync(~0u, lsum, o);
    if (lane == 0) {
        out_idx[(size_t)token * Qq + qstage] = (float)bn;
        atomicAdd(loss, lsum);
    }
}

// ---------------------------------------------------------------------------
// Final: quantized_out = x - residual_final  (one pass)
// ---------------------------------------------------------------------------
__global__ void final_out_kernel(const float4* __restrict__ x,
                                 const float4* __restrict__ residual,
                                 float4* __restrict__ out, int n4)
{
    int i = blockIdx.x * 256 + threadIdx.x;
    if (i < n4) {
        float4 a = x[i], r = residual[i];
        out[i] = make_float4(a.x - r.x, a.y - r.y, a.z - r.z, a.w - r.w);
    }
}

// Tail outputs: all_expired (zeros) then all_losses (mean over B*S*D)
__global__ void finalize_kernel(float* __restrict__ out, const float* __restrict__ loss)
{
    const size_t base = (size_t)Mm * Dd + (size_t)Mm * Qq;
    int t = threadIdx.x;
    if (t < Qq)
        out[base + t] = 0.0f;
    else if (t < 2 * Qq)
        out[base + Qq + (t - Qq)] = loss[t - Qq] * (1.0f / ((float)Mm * (float)Dd));
}

// ---------------------------------------------------------------------------
extern "C" void kernel_launch(void* const* d_in, const int* in_sizes, int n_in,
                              void* d_out, int out_size)
{
    const float* x  = (const float*)d_in[0];   // [B,S,D] f32
    const float* cb = (const float*)d_in[1];   // [Q,K,D] f32
    float* out = (float*)d_out;

    float* residual;   cudaGetSymbolAddress((void**)&residual, g_residual);
    __half* res16;     cudaGetSymbolAddress((void**)&res16,    g_res16);
    __half* cb16;      cudaGetSymbolAddress((void**)&cb16,     g_cb16);
    __half* dist;      cudaGetSymbolAddress((void**)&dist,     g_dist);
    float* c2;         cudaGetSymbolAddress((void**)&c2,       g_c2);
    float* loss;       cudaGetSymbolAddress((void**)&loss,     g_loss);

    cudaFuncSetAttribute(gemm_dist_kernel,
                         cudaFuncAttributeMaxDynamicSharedMemorySize, GEMM_SMEM);

    cudaMemsetAsync(loss, 0, Qq * sizeof(float));

    init_kernel<<<Mm * Dd / 4 / 256, 256>>>((const float4*)x, (float4*)residual,
                                            (__half2*)res16, Mm * Dd / 4);
    conv_kernel<<<(Qq * Kk * Dd / 4 + 255) / 256, 256>>>((const float4*)cb,
                                                         (__half2*)cb16,
                                                         Qq * Kk * Dd / 4);
    c2_kernel<<<Qq * Kk / 8, 256>>>(cb, c2);

    for (int q = 0; q < Qq; ++q) {
        const float* Cq = cb + (size_t)q * Kk * Dd;
        const __half* Cq16 = cb16 + (size_t)q * Kk * Dd;
        dim3 grid(Mm / 128, Kk / 128);
        gemm_dist_kernel<<<grid, 256, GEMM_SMEM>>>(res16, Cq16, c2 + q * Kk, dist);
        refine_update_kernel<<<Mm / 8, 256>>>(dist, residual, res16, Cq,
                                              c2 + q * Kk,
                                              out + (size_t)Mm * Dd, loss + q, q);
    }

    final_out_kernel<<<Mm * Dd / 4 / 256, 256>>>((const float4*)x,
                                                 (const float4*)residual,
                                                 (float4*)out, Mm * Dd / 4);
    finalize_kernel<<<1, 2 * Qq>>>(out, loss);
}